// round 5
// baseline (speedup 1.0000x reference)
#include <cuda_runtime.h>
#include <cuda_bf16.h>
#include <cstdint>
#include <cstddef>

// CCLayer via mma.sync (HMMA bf16, hi/lo split x3 for fp32-grade accuracy).
//   D1[j,p]  = Z_tile^T @ U          (m=cols j, n=p, k=d)
//   w = (alpha - D1) .* Pi ; s = colsum(Pi); Pi pass-through
//   D2[j,d]  = w @ U^T               (m=cols j, n=d, k=p)
//   out = z*s + D2
#define DD 256
#define PP 32
#define TILE 128

#define A_STR  272   // [d][j] bf16 rows: 128*2 + 16 pad (acts as swizzle)
#define U1_STR 528   // [p][d] bf16 rows: 256*2 + 16 pad
#define U2_STR 80    // [d][p] bf16 rows: 32*2 + 16 pad
#define W_STR  80    // [j][p] bf16 rows
#define S2_STR 528   // [dloc][j] f32 rows: 128*4 + 16 pad

#define OFF_A_HI  0          // 256*272 = 69632
#define OFF_A_LO  69632
#define OFF_U1H   139264     // 32*528 = 16896
#define OFF_U1L   156160
#define OFF_U2H   173056     // 256*80 = 20480
#define OFF_U2L   193536
#define OFF_SPART 214016     // 256 f32
#define OFF_SARR  215040     // 128 f32
#define OFF_ALPHA 215552     // 32 f32
#define SMEM_BYTES 215680

// aliases inside the (dead-after-GEMM1) A region
#define OFF_W_HI  (OFF_A_HI)            // 128*80 = 10240
#define OFF_W_LO  (OFF_A_HI + 10240)
#define OFF_S2    (OFF_A_HI + 24576)    // 128*528 = 67584 (ends 92160 < 139264)

#define MMA_BF16(d, a0, a1, a2, a3, b0, b1)                                  \
    asm volatile(                                                            \
        "mma.sync.aligned.m16n8k16.row.col.f32.bf16.bf16.f32 "               \
        "{%0,%1,%2,%3}, {%4,%5,%6,%7}, {%8,%9}, {%0,%1,%2,%3};"              \
        : "+f"(d[0]), "+f"(d[1]), "+f"(d[2]), "+f"(d[3])                     \
        : "r"(a0), "r"(a1), "r"(a2), "r"(a3), "r"(b0), "r"(b1))

#define LDSM_T4(r0, r1, r2, r3, addr)                                        \
    asm volatile(                                                            \
        "ldmatrix.sync.aligned.m8n8.x4.trans.shared.b16 {%0,%1,%2,%3}, [%4];"\
        : "=r"(r0), "=r"(r1), "=r"(r2), "=r"(r3) : "r"(addr))

#define LDS32(r, addr) \
    asm volatile("ld.shared.b32 %0, [%1];" : "=r"(r) : "r"(addr))
#define STS32(addr, v) \
    asm volatile("st.shared.b32 [%0], %1;" :: "r"(addr), "r"(v) : "memory")

__device__ __forceinline__ uint32_t pack_hi2(float a, float b) {
    __nv_bfloat16 ha = __float2bfloat16_rn(a);
    __nv_bfloat16 hb = __float2bfloat16_rn(b);
    return (uint32_t)__bfloat16_as_ushort(ha) |
           ((uint32_t)__bfloat16_as_ushort(hb) << 16);
}
__device__ __forceinline__ uint32_t pack_lo2(float a, float b) {
    __nv_bfloat16 ha = __float2bfloat16_rn(a);
    __nv_bfloat16 hb = __float2bfloat16_rn(b);
    float ra = a - __bfloat162float(ha);
    float rb = b - __bfloat162float(hb);
    return (uint32_t)__bfloat16_as_ushort(__float2bfloat16_rn(ra)) |
           ((uint32_t)__bfloat16_as_ushort(__float2bfloat16_rn(rb)) << 16);
}

__global__ __launch_bounds__(256, 1)
void cclayer_mma(const float* __restrict__ ZPi,
                 const float* __restrict__ U,
                 const float* __restrict__ alpha,
                 float* __restrict__ out,
                 int N, int ntiles) {
    extern __shared__ __align__(128) char smem[];
    uint32_t sbase;
    asm("{ .reg .u64 t; cvta.to.shared.u64 t, %1; cvt.u32.u64 %0, t; }"
        : "=r"(sbase) : "l"(smem));

    const int tid = threadIdx.x;
    const int warp = tid >> 5;
    const int lane = tid & 31;
    const int j0 = warp * 16;            // warp's column rows (m)
    const size_t sN = (size_t)N;

    // ---- persistent U staging: U1[p][d], U2[d][p], hi/lo ----
    for (int i = tid; i < DD * PP; i += 256) {
        const int d = i >> 5, p = i & 31;
        const float v = U[i];
        const __nv_bfloat16 h = __float2bfloat16_rn(v);
        const __nv_bfloat16 l = __float2bfloat16_rn(v - __bfloat162float(h));
        *(uint16_t*)(smem + OFF_U1H + p * U1_STR + d * 2) = __bfloat16_as_ushort(h);
        *(uint16_t*)(smem + OFF_U1L + p * U1_STR + d * 2) = __bfloat16_as_ushort(l);
        *(uint16_t*)(smem + OFF_U2H + d * U2_STR + p * 2) = __bfloat16_as_ushort(h);
        *(uint16_t*)(smem + OFF_U2L + d * U2_STR + p * 2) = __bfloat16_as_ushort(l);
    }
    if (tid < PP) ((float*)(smem + OFF_ALPHA))[tid] = alpha[tid];
    __syncthreads();

    const float* __restrict__ sAlpha = (const float*)(smem + OFF_ALPHA);
    float* __restrict__ sPart = (float*)(smem + OFF_SPART);
    float* __restrict__ sArr = (float*)(smem + OFF_SARR);

    // lane decode for ldmatrix.x4.trans A-fragment addressing ([k][m] source)
    const int krow = (lane & 7) + ((lane >> 4) & 1) * 8;
    const int jcolb = (j0 + ((lane >> 3) & 1) * 8) * 2;
    const uint32_t aHiBase = sbase + OFF_A_HI + krow * A_STR + jcolb;
    const uint32_t aLoBase = sbase + OFF_A_LO + krow * A_STR + jcolb;
    // GEMM1 B base: p = lane/4, dbyte = (lane%4)*4
    const uint32_t b1off = (uint32_t)((lane >> 2) * U1_STR + (lane & 3) * 4);
    // GEMM2 B base: dout = lane/4, pbyte = (lane%4)*4
    const uint32_t b2off = (uint32_t)((lane >> 2) * U2_STR + (lane & 3) * 4);
    // GEMM2 A (w) base: j = j0 + lane/4, pbyte = (lane%4)*4
    const uint32_t wOff = (uint32_t)((j0 + (lane >> 2)) * W_STR + (lane & 3) * 4);

    for (int t = blockIdx.x; t < ntiles; t += gridDim.x) {
        const int col0 = t * TILE;

        // ================= phase 1: Pi pass-through + s, A fill =========
        {
            const int j = tid & 127;
            const int pb = tid >> 7;
            float sp = 0.f;
#pragma unroll
            for (int i = 0; i < 16; i++) {
                const int p = pb + 2 * i;
                const size_t off = (size_t)(DD + p) * sN + col0 + j;
                const float v = ZPi[off];
                out[off] = v;
                sp += v;
            }
            sPart[tid] = sp;
        }
#pragma unroll 4
        for (int it = 0; it < 64; it++) {
            const int task = it * 8 + warp;
            const int d = task >> 1, half = task & 1;
            const float2 v = *(const float2*)(ZPi + (size_t)d * sN + col0 +
                                              half * 64 + 2 * lane);
            const uint32_t soff = d * A_STR + half * 128 + lane * 4;
            *(uint32_t*)(smem + OFF_A_HI + soff) = pack_hi2(v.x, v.y);
            *(uint32_t*)(smem + OFF_A_LO + soff) = pack_lo2(v.x, v.y);
        }
        __syncthreads();
        if (tid < 128) sArr[tid] = sPart[tid] + sPart[tid + 128];

        // ================= GEMM1: D1[16j x 32p], k = 256 ================
        float d1[4][4];
#pragma unroll
        for (int nt = 0; nt < 4; nt++)
#pragma unroll
            for (int q = 0; q < 4; q++) d1[nt][q] = 0.f;

        for (int ks = 0; ks < 16; ks++) {
            uint32_t ah0, ah1, ah2, ah3, al0, al1, al2, al3;
            LDSM_T4(ah0, ah1, ah2, ah3, aHiBase + ks * 16 * A_STR);
            LDSM_T4(al0, al1, al2, al3, aLoBase + ks * 16 * A_STR);
            const uint32_t bh_base = sbase + OFF_U1H + b1off + ks * 32;
            const uint32_t bl_base = sbase + OFF_U1L + b1off + ks * 32;
#pragma unroll
            for (int nt = 0; nt < 4; nt++) {
                uint32_t bh0, bh1, bl0, bl1;
                LDS32(bh0, bh_base + nt * 8 * U1_STR);
                LDS32(bh1, bh_base + nt * 8 * U1_STR + 16);
                LDS32(bl0, bl_base + nt * 8 * U1_STR);
                LDS32(bl1, bl_base + nt * 8 * U1_STR + 16);
                MMA_BF16(d1[nt], ah0, ah1, ah2, ah3, bh0, bh1);
                MMA_BF16(d1[nt], ah0, ah1, ah2, ah3, bl0, bl1);
                MMA_BF16(d1[nt], al0, al1, al2, al3, bh0, bh1);
            }
        }
        __syncthreads();   // all A reads done before w/S2 alias writes

        // ================= epilogue 1: w = (alpha - D1) .* Pi ===========
        {
            const int cj = col0 + j0 + (lane >> 2);
#pragma unroll
            for (int nt = 0; nt < 4; nt++) {
                const int p0 = nt * 8 + 2 * (lane & 3);
                const float a0 = sAlpha[p0], a1 = sAlpha[p0 + 1];
                const float pi00 = ZPi[(size_t)(DD + p0) * sN + cj];
                const float pi10 = ZPi[(size_t)(DD + p0 + 1) * sN + cj];
                const float pi01 = ZPi[(size_t)(DD + p0) * sN + cj + 8];
                const float pi11 = ZPi[(size_t)(DD + p0 + 1) * sN + cj + 8];
                const float w0 = (a0 - d1[nt][0]) * pi00;
                const float w1 = (a1 - d1[nt][1]) * pi10;
                const float w2 = (a0 - d1[nt][2]) * pi01;
                const float w3 = (a1 - d1[nt][3]) * pi11;
                const uint32_t wa = sbase + (uint32_t)((j0 + (lane >> 2)) * W_STR + p0 * 2);
                STS32(wa + OFF_W_HI, pack_hi2(w0, w1));
                STS32(wa + OFF_W_LO, pack_lo2(w0, w1));
                STS32(wa + OFF_W_HI + 8 * W_STR, pack_hi2(w2, w3));
                STS32(wa + OFF_W_LO + 8 * W_STR, pack_lo2(w2, w3));
            }
        }
        __syncwarp();

        // ================= GEMM2 (two halves of 128 d each) =============
#pragma unroll 1
        for (int h = 0; h < 2; h++) {
            float d2[16][4];
#pragma unroll
            for (int nt = 0; nt < 16; nt++)
#pragma unroll
                for (int q = 0; q < 4; q++) d2[nt][q] = 0.f;

#pragma unroll
            for (int ks = 0; ks < 2; ks++) {
                uint32_t ah0, ah1, ah2, ah3, al0, al1, al2, al3;
                const uint32_t wh = sbase + OFF_W_HI + wOff + ks * 32;
                const uint32_t wl = sbase + OFF_W_LO + wOff + ks * 32;
                LDS32(ah0, wh);
                LDS32(ah1, wh + 8 * W_STR);
                LDS32(ah2, wh + 16);
                LDS32(ah3, wh + 8 * W_STR + 16);
                LDS32(al0, wl);
                LDS32(al1, wl + 8 * W_STR);
                LDS32(al2, wl + 16);
                LDS32(al3, wl + 8 * W_STR + 16);
                const uint32_t bh_base = sbase + OFF_U2H + b2off +
                                         (h * 128) * U2_STR + ks * 32;
                const uint32_t bl_base = sbase + OFF_U2L + b2off +
                                         (h * 128) * U2_STR + ks * 32;
#pragma unroll
                for (int nt = 0; nt < 16; nt++) {
                    uint32_t bh0, bh1, bl0, bl1;
                    LDS32(bh0, bh_base + nt * 8 * U2_STR);
                    LDS32(bh1, bh_base + nt * 8 * U2_STR + 16);
                    LDS32(bl0, bl_base + nt * 8 * U2_STR);
                    LDS32(bl1, bl_base + nt * 8 * U2_STR + 16);
                    MMA_BF16(d2[nt], ah0, ah1, ah2, ah3, bh0, bh1);
                    MMA_BF16(d2[nt], ah0, ah1, ah2, ah3, bl0, bl1);
                    MMA_BF16(d2[nt], al0, al1, al2, al3, bh0, bh1);
                }
            }

            // stage D2 fragments into S2 [dloc][j]
#pragma unroll
            for (int nt = 0; nt < 16; nt++) {
                const int r = nt * 8 + 2 * (lane & 3);
                const uint32_t a = sbase + OFF_S2 +
                                   (uint32_t)(r * S2_STR + (j0 + (lane >> 2)) * 4);
                STS32(a, __float_as_uint(d2[nt][0]));
                STS32(a + S2_STR, __float_as_uint(d2[nt][1]));
                STS32(a + 32, __float_as_uint(d2[nt][2]));
                STS32(a + S2_STR + 32, __float_as_uint(d2[nt][3]));
            }
            __syncthreads();

            // coalesced flush: out = z*s + D2
            {
                const int j = tid & 127;
                const int rh = tid >> 7;
                const float sj = sArr[j];
#pragma unroll 4
                for (int i = 0; i < 64; i++) {
                    const int r = i * 2 + rh;
                    const float v = *(const float*)(smem + OFF_S2 + r * S2_STR + j * 4);
                    const size_t off = (size_t)(h * 128 + r) * sN + col0 + j;
                    out[off] = fmaf(ZPi[off], sj, v);
                }
            }
            __syncthreads();
        }
    }
}

extern "C" void kernel_launch(void* const* d_in, const int* in_sizes, int n_in,
                              void* d_out, int out_size) {
    const float* ZPi   = (const float*)d_in[0];
    const float* U     = (const float*)d_in[1];
    const float* alpha = (const float*)d_in[2];
    float* out = (float*)d_out;

    const int N = in_sizes[0] / (DD + PP);
    const int ntiles = N / TILE;

    static int nsm = 0;
    if (nsm == 0) {
        cudaDeviceGetAttribute(&nsm, cudaDevAttrMultiProcessorCount, 0);
        cudaFuncSetAttribute(cclayer_mma, cudaFuncAttributeMaxDynamicSharedMemorySize,
                             SMEM_BYTES);
    }
    const int grid = nsm < ntiles ? nsm : ntiles;
    cclayer_mma<<<grid, 256, SMEM_BYTES>>>(ZPi, U, alpha, out, N, ntiles);
}

// round 7
// speedup vs baseline: 1.2149x; 1.2149x over previous
#include <cuda_runtime.h>
#include <cuda_bf16.h>
#include <cstdint>
#include <cstddef>

// CCLayer via HMMA bf16 (hi/lo split x3), TILE=64, 2 CTAs/SM.
//   D1[j,p] = Z_tile^T @ U ; w = (alpha - D1).*Pi ; s = colsum(Pi)
//   D2[j,d] = w @ U^T ; out[0:256] = z*s + D2 ; out[256:288] = Pi
#define DD 256
#define PP 32
#define TILE 64

#define U1_STR 528           // U1[p][d] bf16 rows: 256*2 + 16 pad
#define D1_STR 140           // D1buf[j] rows: 35 words, gcd(35,32)=1 (conflict-free)
#define W_STR  84            // W[j][p] bf16 rows: 64 + 20 pad

// ---- persistent smem (bytes) ----
#define OFF_A_HI   0         // 256 x 128B rows, XOR-swizzled      (32KB)
#define OFF_A_LO   32768     //                                    (32KB)
#define OFF_U1H    65536     // 32*528 = 16896
#define OFF_U1L    82432
#define OFF_ALPHA  99328     // 32 f32
#define OFF_SPART  99456     // 256 f32
#define SMEM_BYTES 100480

// ---- aliases inside A region (A dead after GEMM1) ----
#define OFF_D1     0         // 2 * 64*140 = 17920
#define D1_KH      8960      // 64*140
#define OFF_W_HI   17920     // 64*84 = 5376
#define OFF_W_LO   23296     // ends 28672 < 32768

#define MMA_BF16(d, a0, a1, a2, a3, b0, b1)                                  \
    asm volatile(                                                            \
        "mma.sync.aligned.m16n8k16.row.col.f32.bf16.bf16.f32 "               \
        "{%0,%1,%2,%3}, {%4,%5,%6,%7}, {%8,%9}, {%0,%1,%2,%3};"              \
        : "+f"(d[0]), "+f"(d[1]), "+f"(d[2]), "+f"(d[3])                     \
        : "r"(a0), "r"(a1), "r"(a2), "r"(a3), "r"(b0), "r"(b1))

#define LDSM_T4(r0, r1, r2, r3, addr)                                        \
    asm volatile(                                                            \
        "ldmatrix.sync.aligned.m8n8.x4.trans.shared.b16 {%0,%1,%2,%3}, [%4];"\
        : "=r"(r0), "=r"(r1), "=r"(r2), "=r"(r3) : "r"(addr))

#define LDS32(r, addr) \
    asm volatile("ld.shared.b32 %0, [%1];" : "=r"(r) : "r"(addr))
#define LDSF(r, addr) \
    asm volatile("ld.shared.f32 %0, [%1];" : "=f"(r) : "r"(addr))
#define STS32(addr, v) \
    asm volatile("st.shared.b32 [%0], %1;" :: "r"(addr), "r"(v) : "memory")
#define STSF(addr, v) \
    asm volatile("st.shared.f32 [%0], %1;" :: "r"(addr), "f"(v) : "memory")

__device__ __forceinline__ uint32_t pack_hi2(float a, float b) {
    __nv_bfloat16 ha = __float2bfloat16_rn(a);
    __nv_bfloat16 hb = __float2bfloat16_rn(b);
    return (uint32_t)__bfloat16_as_ushort(ha) |
           ((uint32_t)__bfloat16_as_ushort(hb) << 16);
}
__device__ __forceinline__ uint32_t pack_lo2(float a, float b) {
    __nv_bfloat16 ha = __float2bfloat16_rn(a);
    __nv_bfloat16 hb = __float2bfloat16_rn(b);
    float ra = a - __bfloat162float(ha);
    float rb = b - __bfloat162float(hb);
    return (uint32_t)__bfloat16_as_ushort(__float2bfloat16_rn(ra)) |
           ((uint32_t)__bfloat16_as_ushort(__float2bfloat16_rn(rb)) << 16);
}

__global__ __launch_bounds__(256, 2)
void cclayer_mma2(const float* __restrict__ ZPi,
                  const float* __restrict__ U,
                  const float* __restrict__ alpha,
                  float* __restrict__ out,
                  int N, int ntiles) {
    extern __shared__ __align__(128) char smem[];
    uint32_t sbase;
    asm("{ .reg .u64 t; cvta.to.shared.u64 t, %1; cvt.u32.u64 %0, t; }"
        : "=r"(sbase) : "l"(smem));

    const int tid = threadIdx.x;
    const int warp = tid >> 5;
    const int lane = tid & 31;
    const size_t sN = (size_t)N;

    // ---- persistent: U1[p][d] hi/lo, alpha ----
    for (int i = tid; i < DD * PP; i += 256) {
        const int d = i >> 5, p = i & 31;
        const float v = U[i];
        const __nv_bfloat16 h = __float2bfloat16_rn(v);
        const __nv_bfloat16 l = __float2bfloat16_rn(v - __bfloat162float(h));
        *(uint16_t*)(smem + OFF_U1H + p * U1_STR + d * 2) = __bfloat16_as_ushort(h);
        *(uint16_t*)(smem + OFF_U1L + p * U1_STR + d * 2) = __bfloat16_as_ushort(l);
    }
    if (tid < PP) ((float*)(smem + OFF_ALPHA))[tid] = alpha[tid];
    __syncthreads();

    const float* __restrict__ sAlpha = (const float*)(smem + OFF_ALPHA);
    float* __restrict__ sPart = (float*)(smem + OFF_SPART);

    // GEMM1 decode: warp = jh + 4*kh
    const int jh = warp & 3;
    const int kh = warp >> 2;
    const int krow_l = (lane & 7) + ((lane >> 4) & 1) * 8;
    const int jcolb = jh * 32 + ((lane >> 3) & 1) * 16;
    const uint32_t b1off = (uint32_t)((lane >> 2) * U1_STR + (lane & 3) * 4);
    // GEMM2 decode: warp = (j-block) + 4*(d-half)
    const int jblk = (warp & 3) * 16;
    const int dh = warp >> 2;
    const uint32_t wOffA = (uint32_t)((jblk + (lane >> 2)) * W_STR + (lane & 3) * 4);
    const int p_l = (lane & 7) + ((lane >> 3) & 1) * 8;
    const int dcol_l = ((lane >> 4) & 1) * 8;
    const int j1 = jblk + (lane >> 2);

    for (int t = blockIdx.x; t < ntiles; t += gridDim.x) {
        const int col0 = t * TILE;

        // ===== phase 1: Z tile -> A hi/lo (swizzled) =====
#pragma unroll 4
        for (int i = 0; i < 32; i++) {
            const int d = warp * 32 + i;
            const float2 v = *(const float2*)(ZPi + (size_t)d * sN + col0 + 2 * lane);
            const uint32_t off = (uint32_t)(d * 128 + lane * 4) ^ (uint32_t)((d & 7) << 4);
            *(uint32_t*)(smem + OFF_A_HI + off) = pack_hi2(v.x, v.y);
            *(uint32_t*)(smem + OFF_A_LO + off) = pack_lo2(v.x, v.y);
        }
        __syncthreads();

        // ===== GEMM1: D1[j,p] partials, k-split =====
        float d1[4][4];
#pragma unroll
        for (int nt = 0; nt < 4; nt++)
#pragma unroll
            for (int q = 0; q < 4; q++) d1[nt][q] = 0.f;

#pragma unroll
        for (int ks = 0; ks < 8; ks++) {
            const int dbase = kh * 128 + ks * 16;
            const int d_l = dbase + krow_l;
            const uint32_t asw = (uint32_t)(d_l * 128 + jcolb) ^ (uint32_t)((d_l & 7) << 4);
            uint32_t ah0, ah1, ah2, ah3, al0, al1, al2, al3;
            LDSM_T4(ah0, ah1, ah2, ah3, sbase + OFF_A_HI + asw);
            LDSM_T4(al0, al1, al2, al3, sbase + OFF_A_LO + asw);
            const uint32_t bh_base = sbase + OFF_U1H + b1off + dbase * 2;
            const uint32_t bl_base = sbase + OFF_U1L + b1off + dbase * 2;
#pragma unroll
            for (int nt = 0; nt < 4; nt++) {
                uint32_t bh0, bh1, bl0, bl1;
                LDS32(bh0, bh_base + nt * 8 * U1_STR);
                LDS32(bh1, bh_base + nt * 8 * U1_STR + 16);
                LDS32(bl0, bl_base + nt * 8 * U1_STR);
                LDS32(bl1, bl_base + nt * 8 * U1_STR + 16);
                MMA_BF16(d1[nt], ah0, ah1, ah2, ah3, bh0, bh1);
                MMA_BF16(d1[nt], ah0, ah1, ah2, ah3, bl0, bl1);
                MMA_BF16(d1[nt], al0, al1, al2, al3, bh0, bh1);
            }
        }
        __syncthreads();   // all A reads done before aliased D1/W writes

        // ---- store D1 partials [kh][j][p] (32-bit stores: D1_STR is 4-aligned) ----
        {
            const uint32_t base = sbase + OFF_D1 + kh * D1_KH;
            const int jr = jh * 16 + (lane >> 2);
#pragma unroll
            for (int nt = 0; nt < 4; nt++) {
                const int p = nt * 8 + 2 * (lane & 3);
                const uint32_t a0 = base + jr * D1_STR + p * 4;
                const uint32_t a1 = base + (jr + 8) * D1_STR + p * 4;
                STSF(a0, d1[nt][0]);
                STSF(a0 + 4, d1[nt][1]);
                STSF(a1, d1[nt][2]);
                STSF(a1 + 4, d1[nt][3]);
            }
        }
        __syncthreads();

        // ===== epilogue 1: w, s, Pi pass-through =====
        {
            const int j = tid & 63;
            const int grp = tid >> 6;
            const size_t c = (size_t)col0 + j;
            float sacc = 0.f;
#pragma unroll
            for (int i = 0; i < 8; i += 2) {
                const int p0 = grp * 8 + i;
                float xa0, xb0, xa1, xb1;
                LDSF(xa0, sbase + OFF_D1 + j * D1_STR + p0 * 4);
                LDSF(xb0, sbase + OFF_D1 + D1_KH + j * D1_STR + p0 * 4);
                LDSF(xa1, sbase + OFF_D1 + j * D1_STR + p0 * 4 + 4);
                LDSF(xb1, sbase + OFF_D1 + D1_KH + j * D1_STR + p0 * 4 + 4);
                const float pi0 = ZPi[(size_t)(DD + p0) * sN + c];
                const float pi1 = ZPi[(size_t)(DD + p0 + 1) * sN + c];
                out[(size_t)(DD + p0) * sN + c] = pi0;
                out[(size_t)(DD + p0 + 1) * sN + c] = pi1;
                sacc += pi0 + pi1;
                const float w0 = (sAlpha[p0] - (xa0 + xb0)) * pi0;
                const float w1 = (sAlpha[p0 + 1] - (xa1 + xb1)) * pi1;
                const uint32_t wa = sbase + (uint32_t)(j * W_STR + p0 * 2);
                STS32(wa + OFF_W_HI, pack_hi2(w0, w1));
                STS32(wa + OFF_W_LO, pack_lo2(w0, w1));
            }
            sPart[grp * 64 + j] = sacc;
        }
        __syncthreads();

        // ===== GEMM2 + fused epilogue 2 =====
        const float s1 = sPart[j1] + sPart[64 + j1] + sPart[128 + j1] + sPart[192 + j1];
        const float s2 = sPart[j1 + 8] + sPart[64 + j1 + 8] + sPart[128 + j1 + 8] + sPart[192 + j1 + 8];

#pragma unroll 1
        for (int h = 0; h < 2; h++) {
            float d2[8][4];
#pragma unroll
            for (int nt = 0; nt < 8; nt++)
#pragma unroll
                for (int q = 0; q < 4; q++) d2[nt][q] = 0.f;

#pragma unroll
            for (int ks = 0; ks < 2; ks++) {
                uint32_t ah0, ah1, ah2, ah3, al0, al1, al2, al3;
                const uint32_t wh = sbase + OFF_W_HI + wOffA + ks * 32;
                const uint32_t wl = sbase + OFF_W_LO + wOffA + ks * 32;
                LDS32(ah0, wh);
                LDS32(ah1, wh + 8 * W_STR);
                LDS32(ah2, wh + 16);
                LDS32(ah3, wh + 8 * W_STR + 16);
                LDS32(al0, wl);
                LDS32(al1, wl + 8 * W_STR);
                LDS32(al2, wl + 16);
                LDS32(al3, wl + 8 * W_STR + 16);
#pragma unroll
                for (int ntp = 0; ntp < 4; ntp++) {
                    const int d0p = dh * 128 + h * 64 + ntp * 16;
                    const uint32_t la = (uint32_t)((ks * 16 + p_l) * U1_STR +
                                                   (d0p + dcol_l) * 2);
                    uint32_t bh0, bh1, bh2, bh3, bl0, bl1, bl2, bl3;
                    LDSM_T4(bh0, bh1, bh2, bh3, sbase + OFF_U1H + la);
                    LDSM_T4(bl0, bl1, bl2, bl3, sbase + OFF_U1L + la);
                    MMA_BF16(d2[2 * ntp], ah0, ah1, ah2, ah3, bh0, bh1);
                    MMA_BF16(d2[2 * ntp], ah0, ah1, ah2, ah3, bl0, bl1);
                    MMA_BF16(d2[2 * ntp], al0, al1, al2, al3, bh0, bh1);
                    MMA_BF16(d2[2 * ntp + 1], ah0, ah1, ah2, ah3, bh2, bh3);
                    MMA_BF16(d2[2 * ntp + 1], ah0, ah1, ah2, ah3, bl2, bl3);
                    MMA_BF16(d2[2 * ntp + 1], al0, al1, al2, al3, bh2, bh3);
                }
            }

            // fused epilogue 2: out = z*s + D2 (32B-sector coalesced)
            const size_t c1 = (size_t)col0 + j1;
#pragma unroll
            for (int nt = 0; nt < 8; nt++) {
                const int d0 = dh * 128 + h * 64 + nt * 8 + 2 * (lane & 3);
                const size_t o00 = (size_t)d0 * sN + c1;
                const size_t o01 = (size_t)(d0 + 1) * sN + c1;
                out[o00] = fmaf(ZPi[o00], s1, d2[nt][0]);
                out[o01] = fmaf(ZPi[o01], s1, d2[nt][1]);
                out[o00 + 8] = fmaf(ZPi[o00 + 8], s2, d2[nt][2]);
                out[o01 + 8] = fmaf(ZPi[o01 + 8], s2, d2[nt][3]);
            }
        }
        __syncthreads();   // W/sPart dead before next tile's phase 1
    }
}

extern "C" void kernel_launch(void* const* d_in, const int* in_sizes, int n_in,
                              void* d_out, int out_size) {
    const float* ZPi   = (const float*)d_in[0];
    const float* U     = (const float*)d_in[1];
    const float* alpha = (const float*)d_in[2];
    float* out = (float*)d_out;

    const int N = in_sizes[0] / (DD + PP);
    const int ntiles = N / TILE;

    static int nsm = 0;
    if (nsm == 0) {
        cudaDeviceGetAttribute(&nsm, cudaDevAttrMultiProcessorCount, 0);
        cudaFuncSetAttribute(cclayer_mma2, cudaFuncAttributeMaxDynamicSharedMemorySize,
                             SMEM_BYTES);
    }
    int grid = 2 * nsm;
    if (grid > ntiles) grid = ntiles;
    cclayer_mma2<<<grid, 256, SMEM_BYTES>>>(ZPi, U, alpha, out, N, ntiles);
}

// round 8
// speedup vs baseline: 1.6821x; 1.3846x over previous
#include <cuda_runtime.h>
#include <cuda_bf16.h>
#include <cstdint>
#include <cstddef>

// CCLayer via HMMA bf16 (hi/lo split x3), TILE=64, 2 CTAs/SM.
//   D1[j,p] = Z_tile^T @ U ; w = (alpha - D1).*Pi ; s = colsum(Pi)
//   D2[j,d] = w @ U^T ; out[0:256] = z*s + D2 ; out[256:288] = Pi
#define DD 256
#define PP 32
#define TILE 64

#define U1_STR 528           // U1[p][d] bf16 rows: 256*2 + 16 pad
#define D1_STR 140           // D1buf[j] rows: 35 words, gcd(35,32)=1 (conflict-free)
#define W_STR  84            // W[j][p] bf16 rows: 64 + 20 pad

// ---- persistent smem (bytes) ----
#define OFF_A_HI   0         // 256 x 128B rows, XOR-swizzled      (32KB)
#define OFF_A_LO   32768     //                                    (32KB)
#define OFF_U1H    65536     // 32*528 = 16896
#define OFF_U1L    82432
#define OFF_ALPHA  99328     // 32 f32
#define OFF_SPART  99456     // 256 f32
#define SMEM_BYTES 100480

// ---- aliases inside A region (A dead after GEMM1) ----
#define OFF_D1     0         // 2 * 64*140 = 17920
#define D1_KH      8960      // 64*140
#define OFF_W_HI   17920     // 64*84 = 5376
#define OFF_W_LO   23296     // ends 28672 < 32768

#define MMA_BF16(d, a0, a1, a2, a3, b0, b1)                                  \
    asm volatile(                                                            \
        "mma.sync.aligned.m16n8k16.row.col.f32.bf16.bf16.f32 "               \
        "{%0,%1,%2,%3}, {%4,%5,%6,%7}, {%8,%9}, {%0,%1,%2,%3};"              \
        : "+f"(d[0]), "+f"(d[1]), "+f"(d[2]), "+f"(d[3])                     \
        : "r"(a0), "r"(a1), "r"(a2), "r"(a3), "r"(b0), "r"(b1))

#define LDSM_T4(r0, r1, r2, r3, addr)                                        \
    asm volatile(                                                            \
        "ldmatrix.sync.aligned.m8n8.x4.trans.shared.b16 {%0,%1,%2,%3}, [%4];"\
        : "=r"(r0), "=r"(r1), "=r"(r2), "=r"(r3) : "r"(addr))

#define LDS32(r, addr) \
    asm volatile("ld.shared.b32 %0, [%1];" : "=r"(r) : "r"(addr))
#define LDSF(r, addr) \
    asm volatile("ld.shared.f32 %0, [%1];" : "=f"(r) : "r"(addr))
#define STS32(addr, v) \
    asm volatile("st.shared.b32 [%0], %1;" :: "r"(addr), "r"(v) : "memory")
#define STSF(addr, v) \
    asm volatile("st.shared.f32 [%0], %1;" :: "r"(addr), "f"(v) : "memory")

__device__ __forceinline__ uint32_t pack_hi2(float a, float b) {
    __nv_bfloat16 ha = __float2bfloat16_rn(a);
    __nv_bfloat16 hb = __float2bfloat16_rn(b);
    return (uint32_t)__bfloat16_as_ushort(ha) |
           ((uint32_t)__bfloat16_as_ushort(hb) << 16);
}
__device__ __forceinline__ uint32_t pack_lo2(float a, float b) {
    __nv_bfloat16 ha = __float2bfloat16_rn(a);
    __nv_bfloat16 hb = __float2bfloat16_rn(b);
    float ra = a - __bfloat162float(ha);
    float rb = b - __bfloat162float(hb);
    return (uint32_t)__bfloat16_as_ushort(__float2bfloat16_rn(ra)) |
           ((uint32_t)__bfloat16_as_ushort(__float2bfloat16_rn(rb)) << 16);
}

__global__ __launch_bounds__(256, 2)
void cclayer_mma2(const float* __restrict__ ZPi,
                  const float* __restrict__ U,
                  const float* __restrict__ alpha,
                  float* __restrict__ out,
                  int N, int ntiles) {
    extern __shared__ __align__(128) char smem[];
    uint32_t sbase;
    asm("{ .reg .u64 t; cvta.to.shared.u64 t, %1; cvt.u32.u64 %0, t; }"
        : "=r"(sbase) : "l"(smem));

    const int tid = threadIdx.x;
    const int warp = tid >> 5;
    const int lane = tid & 31;
    const size_t sN = (size_t)N;

    // ---- persistent: U1[p][d] hi/lo, alpha ----
    for (int i = tid; i < DD * PP; i += 256) {
        const int d = i >> 5, p = i & 31;
        const float v = U[i];
        const __nv_bfloat16 h = __float2bfloat16_rn(v);
        const __nv_bfloat16 l = __float2bfloat16_rn(v - __bfloat162float(h));
        *(uint16_t*)(smem + OFF_U1H + p * U1_STR + d * 2) = __bfloat16_as_ushort(h);
        *(uint16_t*)(smem + OFF_U1L + p * U1_STR + d * 2) = __bfloat16_as_ushort(l);
    }
    if (tid < PP) ((float*)(smem + OFF_ALPHA))[tid] = alpha[tid];
    __syncthreads();

    const float* __restrict__ sAlpha = (const float*)(smem + OFF_ALPHA);
    float* __restrict__ sPart = (float*)(smem + OFF_SPART);

    // GEMM1 decode: warp = jh + 4*kh
    const int jh = warp & 3;
    const int kh = warp >> 2;
    const int krow_l = (lane & 7) + ((lane >> 4) & 1) * 8;
    const int jcolb = jh * 32 + ((lane >> 3) & 1) * 16;
    const uint32_t b1off = (uint32_t)((lane >> 2) * U1_STR + (lane & 3) * 4);
    // GEMM2 decode: warp = (j-block) + 4*(d-half)
    const int jblk = (warp & 3) * 16;
    const int dh = warp >> 2;
    const uint32_t wOffA = (uint32_t)((jblk + (lane >> 2)) * W_STR + (lane & 3) * 4);
    const int p_l = (lane & 7) + ((lane >> 3) & 1) * 8;
    const int dcol_l = ((lane >> 4) & 1) * 8;
    const int j1 = jblk + (lane >> 2);

    for (int t = blockIdx.x; t < ntiles; t += gridDim.x) {
        const int col0 = t * TILE;

        // ===== phase 1: Z tile -> A hi/lo (swizzled) =====
#pragma unroll 4
        for (int i = 0; i < 32; i++) {
            const int d = warp * 32 + i;
            const float2 v = *(const float2*)(ZPi + (size_t)d * sN + col0 + 2 * lane);
            const uint32_t off = (uint32_t)(d * 128 + lane * 4) ^ (uint32_t)((d & 7) << 4);
            *(uint32_t*)(smem + OFF_A_HI + off) = pack_hi2(v.x, v.y);
            *(uint32_t*)(smem + OFF_A_LO + off) = pack_lo2(v.x, v.y);
        }
        __syncthreads();

        // ===== GEMM1: D1[j,p] partials, k-split =====
        float d1[4][4];
#pragma unroll
        for (int nt = 0; nt < 4; nt++)
#pragma unroll
            for (int q = 0; q < 4; q++) d1[nt][q] = 0.f;

#pragma unroll
        for (int ks = 0; ks < 8; ks++) {
            const int dbase = kh * 128 + ks * 16;
            const int d_l = dbase + krow_l;
            const uint32_t asw = (uint32_t)(d_l * 128 + jcolb) ^ (uint32_t)((d_l & 7) << 4);
            uint32_t ah0, ah1, ah2, ah3, al0, al1, al2, al3;
            LDSM_T4(ah0, ah1, ah2, ah3, sbase + OFF_A_HI + asw);
            LDSM_T4(al0, al1, al2, al3, sbase + OFF_A_LO + asw);
            const uint32_t bh_base = sbase + OFF_U1H + b1off + dbase * 2;
            const uint32_t bl_base = sbase + OFF_U1L + b1off + dbase * 2;
#pragma unroll
            for (int nt = 0; nt < 4; nt++) {
                uint32_t bh0, bh1, bl0, bl1;
                LDS32(bh0, bh_base + nt * 8 * U1_STR);
                LDS32(bh1, bh_base + nt * 8 * U1_STR + 16);
                LDS32(bl0, bl_base + nt * 8 * U1_STR);
                LDS32(bl1, bl_base + nt * 8 * U1_STR + 16);
                MMA_BF16(d1[nt], ah0, ah1, ah2, ah3, bh0, bh1);
                MMA_BF16(d1[nt], ah0, ah1, ah2, ah3, bl0, bl1);
                MMA_BF16(d1[nt], al0, al1, al2, al3, bh0, bh1);
            }
        }
        __syncthreads();   // all A reads done before aliased D1/W writes

        // ---- store D1 partials [kh][j][p] (32-bit stores: D1_STR is 4-aligned) ----
        {
            const uint32_t base = sbase + OFF_D1 + kh * D1_KH;
            const int jr = jh * 16 + (lane >> 2);
#pragma unroll
            for (int nt = 0; nt < 4; nt++) {
                const int p = nt * 8 + 2 * (lane & 3);
                const uint32_t a0 = base + jr * D1_STR + p * 4;
                const uint32_t a1 = base + (jr + 8) * D1_STR + p * 4;
                STSF(a0, d1[nt][0]);
                STSF(a0 + 4, d1[nt][1]);
                STSF(a1, d1[nt][2]);
                STSF(a1 + 4, d1[nt][3]);
            }
        }
        __syncthreads();

        // ===== epilogue 1: w, s, Pi pass-through =====
        {
            const int j = tid & 63;
            const int grp = tid >> 6;
            const size_t c = (size_t)col0 + j;
            float sacc = 0.f;
#pragma unroll
            for (int i = 0; i < 8; i += 2) {
                const int p0 = grp * 8 + i;
                float xa0, xb0, xa1, xb1;
                LDSF(xa0, sbase + OFF_D1 + j * D1_STR + p0 * 4);
                LDSF(xb0, sbase + OFF_D1 + D1_KH + j * D1_STR + p0 * 4);
                LDSF(xa1, sbase + OFF_D1 + j * D1_STR + p0 * 4 + 4);
                LDSF(xb1, sbase + OFF_D1 + D1_KH + j * D1_STR + p0 * 4 + 4);
                const float pi0 = ZPi[(size_t)(DD + p0) * sN + c];
                const float pi1 = ZPi[(size_t)(DD + p0 + 1) * sN + c];
                out[(size_t)(DD + p0) * sN + c] = pi0;
                out[(size_t)(DD + p0 + 1) * sN + c] = pi1;
                sacc += pi0 + pi1;
                const float w0 = (sAlpha[p0] - (xa0 + xb0)) * pi0;
                const float w1 = (sAlpha[p0 + 1] - (xa1 + xb1)) * pi1;
                const uint32_t wa = sbase + (uint32_t)(j * W_STR + p0 * 2);
                STS32(wa + OFF_W_HI, pack_hi2(w0, w1));
                STS32(wa + OFF_W_LO, pack_lo2(w0, w1));
            }
            sPart[grp * 64 + j] = sacc;
        }
        __syncthreads();

        // ===== GEMM2 + fused epilogue 2 =====
        const float s1 = sPart[j1] + sPart[64 + j1] + sPart[128 + j1] + sPart[192 + j1];
        const float s2 = sPart[j1 + 8] + sPart[64 + j1 + 8] + sPart[128 + j1 + 8] + sPart[192 + j1 + 8];

#pragma unroll 1
        for (int h = 0; h < 2; h++) {
            float d2[8][4];
#pragma unroll
            for (int nt = 0; nt < 8; nt++)
#pragma unroll
                for (int q = 0; q < 4; q++) d2[nt][q] = 0.f;

#pragma unroll
            for (int ks = 0; ks < 2; ks++) {
                uint32_t ah0, ah1, ah2, ah3, al0, al1, al2, al3;
                const uint32_t wh = sbase + OFF_W_HI + wOffA + ks * 32;
                const uint32_t wl = sbase + OFF_W_LO + wOffA + ks * 32;
                LDS32(ah0, wh);
                LDS32(ah1, wh + 8 * W_STR);
                LDS32(ah2, wh + 16);
                LDS32(ah3, wh + 8 * W_STR + 16);
                LDS32(al0, wl);
                LDS32(al1, wl + 8 * W_STR);
                LDS32(al2, wl + 16);
                LDS32(al3, wl + 8 * W_STR + 16);
#pragma unroll
                for (int ntp = 0; ntp < 4; ntp++) {
                    const int d0p = dh * 128 + h * 64 + ntp * 16;
                    const uint32_t la = (uint32_t)((ks * 16 + p_l) * U1_STR +
                                                   (d0p + dcol_l) * 2);
                    uint32_t bh0, bh1, bh2, bh3, bl0, bl1, bl2, bl3;
                    LDSM_T4(bh0, bh1, bh2, bh3, sbase + OFF_U1H + la);
                    LDSM_T4(bl0, bl1, bl2, bl3, sbase + OFF_U1L + la);
                    MMA_BF16(d2[2 * ntp], ah0, ah1, ah2, ah3, bh0, bh1);
                    MMA_BF16(d2[2 * ntp], ah0, ah1, ah2, ah3, bl0, bl1);
                    MMA_BF16(d2[2 * ntp], al0, al1, al2, al3, bh0, bh1);
                    MMA_BF16(d2[2 * ntp + 1], ah0, ah1, ah2, ah3, bh2, bh3);
                    MMA_BF16(d2[2 * ntp + 1], ah0, ah1, ah2, ah3, bl2, bl3);
                    MMA_BF16(d2[2 * ntp + 1], al0, al1, al2, al3, bh2, bh3);
                }
            }

            // fused epilogue 2: out = z*s + D2 (32B-sector coalesced)
            const size_t c1 = (size_t)col0 + j1;
#pragma unroll
            for (int nt = 0; nt < 8; nt++) {
                const int d0 = dh * 128 + h * 64 + nt * 8 + 2 * (lane & 3);
                const size_t o00 = (size_t)d0 * sN + c1;
                const size_t o01 = (size_t)(d0 + 1) * sN + c1;
                out[o00] = fmaf(ZPi[o00], s1, d2[nt][0]);
                out[o01] = fmaf(ZPi[o01], s1, d2[nt][1]);
                out[o00 + 8] = fmaf(ZPi[o00 + 8], s2, d2[nt][2]);
                out[o01 + 8] = fmaf(ZPi[o01 + 8], s2, d2[nt][3]);
            }
        }
        __syncthreads();   // W/sPart dead before next tile's phase 1
    }
}

extern "C" void kernel_launch(void* const* d_in, const int* in_sizes, int n_in,
                              void* d_out, int out_size) {
    const float* ZPi   = (const float*)d_in[0];
    const float* U     = (const float*)d_in[1];
    const float* alpha = (const float*)d_in[2];
    float* out = (float*)d_out;

    const int N = in_sizes[0] / (DD + PP);
    const int ntiles = N / TILE;

    static int nsm = 0;
    if (nsm == 0) {
        cudaDeviceGetAttribute(&nsm, cudaDevAttrMultiProcessorCount, 0);
        cudaFuncSetAttribute(cclayer_mma2, cudaFuncAttributeMaxDynamicSharedMemorySize,
                             SMEM_BYTES);
    }
    int grid = 2 * nsm;
    if (grid > ntiles) grid = ntiles;
    cclayer_mma2<<<grid, 256, SMEM_BYTES>>>(ZPi, U, alpha, out, N, ntiles);
}

// round 9
// speedup vs baseline: 1.7075x; 1.0151x over previous
#include <cuda_runtime.h>
#include <cuda_bf16.h>
#include <cstdint>
#include <cstddef>

// CCLayer via HMMA bf16 (hi/lo split x3), TILE=64, 512 threads, 2 CTAs/SM.
//   D1[j,p] = Z_tile^T @ U ; w = (alpha - D1).*Pi ; s = colsum(Pi)
//   D2[j,d] = w @ U^T ; out[0:256] = z*s + D2 ; out[256:288] = Pi
#define DD 256
#define PP 32
#define TILE 64
#define THREADS 512

#define U1_STR 528           // U1[p][d] bf16 rows: 256*2 + 16 pad
#define D1_STR 140           // D1buf[j] rows: 35 words, gcd(35,32)=1
#define W_STR  84            // W[j][p] bf16 rows: 64 + 20 pad

// ---- persistent smem (bytes) ----
#define OFF_A_HI   0         // 256 x 128B rows, XOR-swizzled      (32KB)
#define OFF_A_LO   32768     //                                    (32KB)
#define OFF_U1H    65536     // 32*528 = 16896
#define OFF_U1L    82432
#define OFF_ALPHA  99328     // 32 f32
#define OFF_SPART  99456     // 8*64 f32 = 2048
#define SMEM_BYTES 101504

// ---- aliases inside A region (A dead after GEMM1) ----
#define OFF_D1     0         // 4 * 64*140 = 35840
#define D1_KH      8960      // 64*140
#define OFF_W_HI   35840     // 64*84 = 5376
#define OFF_W_LO   41216     // ends 46592 < 65536

#define MMA_BF16(d, a0, a1, a2, a3, b0, b1)                                  \
    asm volatile(                                                            \
        "mma.sync.aligned.m16n8k16.row.col.f32.bf16.bf16.f32 "               \
        "{%0,%1,%2,%3}, {%4,%5,%6,%7}, {%8,%9}, {%0,%1,%2,%3};"              \
        : "+f"(d[0]), "+f"(d[1]), "+f"(d[2]), "+f"(d[3])                     \
        : "r"(a0), "r"(a1), "r"(a2), "r"(a3), "r"(b0), "r"(b1))

#define LDSM_T4(r0, r1, r2, r3, addr)                                        \
    asm volatile(                                                            \
        "ldmatrix.sync.aligned.m8n8.x4.trans.shared.b16 {%0,%1,%2,%3}, [%4];"\
        : "=r"(r0), "=r"(r1), "=r"(r2), "=r"(r3) : "r"(addr))

#define LDS32(r, addr) \
    asm volatile("ld.shared.b32 %0, [%1];" : "=r"(r) : "r"(addr))
#define LDSF(r, addr) \
    asm volatile("ld.shared.f32 %0, [%1];" : "=f"(r) : "r"(addr))
#define STS32(addr, v) \
    asm volatile("st.shared.b32 [%0], %1;" :: "r"(addr), "r"(v) : "memory")
#define STSF(addr, v) \
    asm volatile("st.shared.f32 [%0], %1;" :: "r"(addr), "f"(v) : "memory")

__device__ __forceinline__ uint32_t pack_hi2(float a, float b) {
    __nv_bfloat16 ha = __float2bfloat16_rn(a);
    __nv_bfloat16 hb = __float2bfloat16_rn(b);
    return (uint32_t)__bfloat16_as_ushort(ha) |
           ((uint32_t)__bfloat16_as_ushort(hb) << 16);
}
__device__ __forceinline__ uint32_t pack_lo2(float a, float b) {
    __nv_bfloat16 ha = __float2bfloat16_rn(a);
    __nv_bfloat16 hb = __float2bfloat16_rn(b);
    float ra = a - __bfloat162float(ha);
    float rb = b - __bfloat162float(hb);
    return (uint32_t)__bfloat16_as_ushort(__float2bfloat16_rn(ra)) |
           ((uint32_t)__bfloat16_as_ushort(__float2bfloat16_rn(rb)) << 16);
}

__global__ __launch_bounds__(THREADS, 2)
void cclayer_mma3(const float* __restrict__ ZPi,
                  const float* __restrict__ U,
                  const float* __restrict__ alpha,
                  float* __restrict__ out,
                  int N, int ntiles) {
    extern __shared__ __align__(128) char smem[];
    uint32_t sbase;
    asm("{ .reg .u64 t; cvta.to.shared.u64 t, %1; cvt.u32.u64 %0, t; }"
        : "=r"(sbase) : "l"(smem));

    const int tid = threadIdx.x;
    const int warp = tid >> 5;
    const int lane = tid & 31;
    const size_t sN = (size_t)N;

    // ---- persistent: U1[p][d] hi/lo, alpha ----
    for (int i = tid; i < DD * PP; i += THREADS) {
        const int d = i >> 5, p = i & 31;
        const float v = U[i];
        const __nv_bfloat16 h = __float2bfloat16_rn(v);
        const __nv_bfloat16 l = __float2bfloat16_rn(v - __bfloat162float(h));
        *(uint16_t*)(smem + OFF_U1H + p * U1_STR + d * 2) = __bfloat16_as_ushort(h);
        *(uint16_t*)(smem + OFF_U1L + p * U1_STR + d * 2) = __bfloat16_as_ushort(l);
    }
    if (tid < PP) ((float*)(smem + OFF_ALPHA))[tid] = alpha[tid];
    __syncthreads();

    const float* __restrict__ sAlpha = (const float*)(smem + OFF_ALPHA);

    // GEMM1 decode: warp = jh + 4*kq  (4 j-blocks x 4 k-quarters)
    const int jh = warp & 3;
    const int kq = warp >> 2;
    const int krow_l = (lane & 7) + ((lane >> 4) & 1) * 8;
    const int jcolb = jh * 32 + ((lane >> 3) & 1) * 16;
    const uint32_t b1off = (uint32_t)((lane >> 2) * U1_STR + (lane & 3) * 4);
    // GEMM2 decode: warp = jblk + 4*dq (4 j-blocks x 4 d-quarters)
    const int jblk = (warp & 3) * 16;
    const int dq = warp >> 2;
    const uint32_t wOffA = (uint32_t)((jblk + (lane >> 2)) * W_STR + (lane & 3) * 4);
    const int p_l = (lane & 7) + ((lane >> 3) & 1) * 8;
    const int dcol_l = ((lane >> 4) & 1) * 8;
    const int j1 = jblk + (lane >> 2);

    for (int t = blockIdx.x; t < ntiles; t += gridDim.x) {
        const int col0 = t * TILE;

        // ===== phase 1: Z tile -> A hi/lo (swizzled) =====
#pragma unroll 4
        for (int i = 0; i < 16; i++) {
            const int d = warp * 16 + i;
            const float2 v = *(const float2*)(ZPi + (size_t)d * sN + col0 + 2 * lane);
            const uint32_t off = (uint32_t)(d * 128 + lane * 4) ^ (uint32_t)((d & 7) << 4);
            *(uint32_t*)(smem + OFF_A_HI + off) = pack_hi2(v.x, v.y);
            *(uint32_t*)(smem + OFF_A_LO + off) = pack_lo2(v.x, v.y);
        }
        __syncthreads();

        // ===== GEMM1: D1[j,p] partials, k-split 4 =====
        float d1[4][4];
#pragma unroll
        for (int nt = 0; nt < 4; nt++)
#pragma unroll
            for (int q = 0; q < 4; q++) d1[nt][q] = 0.f;

#pragma unroll
        for (int ks = 0; ks < 4; ks++) {
            const int dbase = kq * 64 + ks * 16;
            const int d_l = dbase + krow_l;
            const uint32_t asw = (uint32_t)(d_l * 128 + jcolb) ^ (uint32_t)((d_l & 7) << 4);
            uint32_t ah0, ah1, ah2, ah3, al0, al1, al2, al3;
            LDSM_T4(ah0, ah1, ah2, ah3, sbase + OFF_A_HI + asw);
            LDSM_T4(al0, al1, al2, al3, sbase + OFF_A_LO + asw);
            const uint32_t bh_base = sbase + OFF_U1H + b1off + dbase * 2;
            const uint32_t bl_base = sbase + OFF_U1L + b1off + dbase * 2;
#pragma unroll
            for (int nt = 0; nt < 4; nt++) {
                uint32_t bh0, bh1, bl0, bl1;
                LDS32(bh0, bh_base + nt * 8 * U1_STR);
                LDS32(bh1, bh_base + nt * 8 * U1_STR + 16);
                LDS32(bl0, bl_base + nt * 8 * U1_STR);
                LDS32(bl1, bl_base + nt * 8 * U1_STR + 16);
                MMA_BF16(d1[nt], ah0, ah1, ah2, ah3, bh0, bh1);
                MMA_BF16(d1[nt], ah0, ah1, ah2, ah3, bl0, bl1);
                MMA_BF16(d1[nt], al0, al1, al2, al3, bh0, bh1);
            }
        }
        __syncthreads();   // all A reads done before aliased D1/W writes

        // ---- store D1 partials [kq][j][p] (32-bit stores) ----
        {
            const uint32_t base = sbase + OFF_D1 + kq * D1_KH;
            const int jr = jh * 16 + (lane >> 2);
#pragma unroll
            for (int nt = 0; nt < 4; nt++) {
                const int p = nt * 8 + 2 * (lane & 3);
                const uint32_t a0 = base + jr * D1_STR + p * 4;
                const uint32_t a1 = base + (jr + 8) * D1_STR + p * 4;
                STSF(a0, d1[nt][0]);
                STSF(a0 + 4, d1[nt][1]);
                STSF(a1, d1[nt][2]);
                STSF(a1 + 4, d1[nt][3]);
            }
        }
        __syncthreads();

        // ===== epilogue 1: w, s, Pi pass-through (8 p-groups x 64 j) =====
        {
            const int j = tid & 63;
            const int pg = tid >> 6;          // 0..7, 4 p's each
            const int p0 = pg * 4;
            const size_t c = (size_t)col0 + j;
            const uint32_t db = sbase + OFF_D1 + j * D1_STR;
            float sacc = 0.f;
            float wv[4];
#pragma unroll
            for (int i = 0; i < 4; i++) {
                const int p = p0 + i;
                float x0, x1, x2, x3;
                LDSF(x0, db + p * 4);
                LDSF(x1, db + D1_KH + p * 4);
                LDSF(x2, db + 2 * D1_KH + p * 4);
                LDSF(x3, db + 3 * D1_KH + p * 4);
                const float pi = ZPi[(size_t)(DD + p) * sN + c];
                out[(size_t)(DD + p) * sN + c] = pi;
                sacc += pi;
                wv[i] = (sAlpha[p] - ((x0 + x1) + (x2 + x3))) * pi;
            }
            const uint32_t wa = sbase + (uint32_t)(j * W_STR + p0 * 2);
            STS32(wa + OFF_W_HI, pack_hi2(wv[0], wv[1]));
            STS32(wa + OFF_W_LO, pack_lo2(wv[0], wv[1]));
            STS32(wa + OFF_W_HI + 4, pack_hi2(wv[2], wv[3]));
            STS32(wa + OFF_W_LO + 4, pack_lo2(wv[2], wv[3]));
            ((float*)(smem + OFF_SPART))[pg * 64 + j] = sacc;
        }
        __syncthreads();

        // ===== GEMM2 + fused epilogue 2 =====
        float s1 = 0.f, s2 = 0.f;
        {
            const float* sp = (const float*)(smem + OFF_SPART);
#pragma unroll
            for (int gq = 0; gq < 8; gq++) {
                s1 += sp[gq * 64 + j1];
                s2 += sp[gq * 64 + j1 + 8];
            }
        }

#pragma unroll 1
        for (int h = 0; h < 2; h++) {         // two 32-d halves of this quarter
            float d2[4][4];
#pragma unroll
            for (int nt = 0; nt < 4; nt++)
#pragma unroll
                for (int q = 0; q < 4; q++) d2[nt][q] = 0.f;

#pragma unroll
            for (int ks = 0; ks < 2; ks++) {
                uint32_t ah0, ah1, ah2, ah3, al0, al1, al2, al3;
                const uint32_t wh = sbase + OFF_W_HI + wOffA + ks * 32;
                const uint32_t wl = sbase + OFF_W_LO + wOffA + ks * 32;
                LDS32(ah0, wh);
                LDS32(ah1, wh + 8 * W_STR);
                LDS32(ah2, wh + 16);
                LDS32(ah3, wh + 8 * W_STR + 16);
                LDS32(al0, wl);
                LDS32(al1, wl + 8 * W_STR);
                LDS32(al2, wl + 16);
                LDS32(al3, wl + 8 * W_STR + 16);
#pragma unroll
                for (int ntp = 0; ntp < 2; ntp++) {
                    const int d0p = dq * 64 + h * 32 + ntp * 16;
                    const uint32_t la = (uint32_t)((ks * 16 + p_l) * U1_STR +
                                                   (d0p + dcol_l) * 2);
                    uint32_t bh0, bh1, bh2, bh3, bl0, bl1, bl2, bl3;
                    LDSM_T4(bh0, bh1, bh2, bh3, sbase + OFF_U1H + la);
                    LDSM_T4(bl0, bl1, bl2, bl3, sbase + OFF_U1L + la);
                    MMA_BF16(d2[2 * ntp], ah0, ah1, ah2, ah3, bh0, bh1);
                    MMA_BF16(d2[2 * ntp], ah0, ah1, ah2, ah3, bl0, bl1);
                    MMA_BF16(d2[2 * ntp], al0, al1, al2, al3, bh0, bh1);
                    MMA_BF16(d2[2 * ntp + 1], ah0, ah1, ah2, ah3, bh2, bh3);
                    MMA_BF16(d2[2 * ntp + 1], ah0, ah1, ah2, ah3, bl2, bl3);
                    MMA_BF16(d2[2 * ntp + 1], al0, al1, al2, al3, bh2, bh3);
                }
            }

            // fused epilogue 2: out = z*s + D2 (32B-sector coalesced)
            const size_t c1 = (size_t)col0 + j1;
#pragma unroll
            for (int nt = 0; nt < 4; nt++) {
                const int d0 = dq * 64 + h * 32 + nt * 8 + 2 * (lane & 3);
                const size_t o00 = (size_t)d0 * sN + c1;
                const size_t o01 = (size_t)(d0 + 1) * sN + c1;
                out[o00] = fmaf(ZPi[o00], s1, d2[nt][0]);
                out[o01] = fmaf(ZPi[o01], s1, d2[nt][1]);
                out[o00 + 8] = fmaf(ZPi[o00 + 8], s2, d2[nt][2]);
                out[o01 + 8] = fmaf(ZPi[o01 + 8], s2, d2[nt][3]);
            }
        }
        __syncthreads();   // W/sPart dead before next tile's phase 1
    }
}

extern "C" void kernel_launch(void* const* d_in, const int* in_sizes, int n_in,
                              void* d_out, int out_size) {
    const float* ZPi   = (const float*)d_in[0];
    const float* U     = (const float*)d_in[1];
    const float* alpha = (const float*)d_in[2];
    float* out = (float*)d_out;

    const int N = in_sizes[0] / (DD + PP);
    const int ntiles = N / TILE;

    static int nsm = 0;
    if (nsm == 0) {
        cudaDeviceGetAttribute(&nsm, cudaDevAttrMultiProcessorCount, 0);
        cudaFuncSetAttribute(cclayer_mma3, cudaFuncAttributeMaxDynamicSharedMemorySize,
                             SMEM_BYTES);
    }
    int grid = 2 * nsm;
    if (grid > ntiles) grid = ntiles;
    cclayer_mma3<<<grid, THREADS, SMEM_BYTES>>>(ZPi, U, alpha, out, N, ntiles);
}